// round 5
// baseline (speedup 1.0000x reference)
#include <cuda_runtime.h>
#include <math.h>

#define W_IMG 4096
// float(pi) - pi  (cos(pi_f) == -1 exactly, sin(pi_f) == -DPI)
#define DPI 8.742278e-8f
#define ZMIN 1e-12f

__device__ __forceinline__ float rcpa(float x){ float y; asm("rcp.approx.f32 %0, %1;" : "=f"(y) : "f"(x)); return y; }
__device__ __forceinline__ float rsqa(float x){ float y; asm("rsqrt.approx.f32 %0, %1;" : "=f"(y) : "f"(x)); return y; }
// y with sign flipped by sign(x): single LOP3
__device__ __forceinline__ float xsign(float y, float x){
    return __int_as_float(__float_as_int(y) ^ (__float_as_int(x) & 0x80000000u));
}

// ---------- robust sin/cos of atan(num/den): handles inf operands too -------
__device__ __forceinline__ void cs_atan_core(float num, float den, float& sa, float& ca) {
    float an = fabsf(num), ad = fabsf(den);
    bool sw = an > ad;
    float top = sw ? den : num;
    float bot = sw ? num : den;
    float q  = top * rcpa(bot);                 // |q| <= 1, or NaN
    float rr = rsqa(fmaf(q, q, 1.f));
    float sg = copysignf(1.f, num) * copysignf(1.f, den);
    ca = sw ? fabsf(q) * rr : rr;
    sa = sw ? sg * rr : q * rr;
}

// ---------- HOT finisher: nx_t, ny_t guaranteed finite (z > ZMIN) -----------
__device__ __forceinline__ void hot_finish(
    float nx_t, float ny_t,
    const float* Xd, const float* Yd, const float* Zd,
    int sf, float& onx, float& ony, float& onz)
{
    float nt2 = fmaf(nx_t, nx_t, ny_t * ny_t);
    float r0  = rsqa(nt2);
    float ca  = fabsf(nx_t) * r0;           // cos(atan(ny/nx))
    float sa  = xsign(ny_t, nx_t) * r0;     // sin(atan(ny/nx))
    float a   = fmaf(sa, DPI, -ca);         // cos(atan + pi_f)
    float b   = -fmaf(ca, DPI, sa);         // sin(atan + pi_f)

    float rnz[4], nzv[4];
    int npos = 0, nneg = 0;
#pragma unroll
    for (int i = 0; i < 4; i++) {
        float nz_i = -fmaf(nx_t, Xd[i], ny_t * Yd[i]) * rcpa(Zd[i]);
        float rn = rsqa(fmaf(nz_i, nz_i, nt2));
        float v  = nz_i * rn;
        rnz[i] = (rn != rn) ? 0.f : rn;
        nzv[i] = (v  != v)  ? 0.f : v;
        npos += nzv[i] > 0.f;
        nneg += nzv[i] < 0.f;
    }

    float srn = 0.f, snz = 0.f;
    if (sf) {
        bool ps = npos >= nneg;
#pragma unroll
        for (int i = 0; i < 4; i++) {
            float fm = (ps ? (nzv[i] > 0.f) : (nzv[i] < 0.f)) ? 1.f : 0.f;
            srn = fmaf(fm, rnz[i], srn);
            snz = fmaf(fm, nzv[i], snz);
        }
    } else {
#pragma unroll
        for (int i = 0; i < 4; i++) { srn += rnz[i]; snz += nzv[i]; }
    }

    // snx*a + sny*b == srn * (-sign(nx_t)) * sqrt(nt2)   (exact; DPI cancels)
    float num = -xsign(srn * (nt2 * r0), nx_t);
    float rr  = rsqa(fmaf(num, num, snz * snz));
    float st  = xsign(num, snz) * rr;       // sin(atan(num/snz))
    float ct  = fabsf(snz) * rr;            // cos(atan(num/snz))
    float nx = st * a, ny = st * b, nz = ct;
    if (nz != nz) { nx = 0.f; ny = 0.f; nz = -1.f; }
    float s = (ny > 0.f) ? -1.f : 1.f;
    onx = nx * s; ony = ny * s; onz = nz * s;
}

// ---------- generic finisher (robust to inf nx_t/ny_t) ----------------------
__device__ __forceinline__ void gen_finish(
    float nx_t, float ny_t,
    const float* Xd, const float* Yd, const float* Zd,
    int sf, float& onx, float& ony, float& onz)
{
    float sa, ca; cs_atan_core(ny_t, nx_t, sa, ca);
    float a = fmaf(sa, DPI, -ca);
    float b = -fmaf(ca, DPI, sa);
    float nt2 = fmaf(nx_t, nx_t, ny_t * ny_t);

    float nxv[4], nyv[4], nzv[4];
#pragma unroll
    for (int i = 0; i < 4; i++) {
        float nz_i = -fmaf(nx_t, Xd[i], ny_t * Yd[i]) * rcpa(Zd[i]);
        float rn = rsqa(fmaf(nz_i, nz_i, nt2));
        float vx = nx_t * rn, vy = ny_t * rn, vz = nz_i * rn;
        nxv[i] = (vx != vx) ? 0.f : vx;
        nyv[i] = (vy != vy) ? 0.f : vy;
        nzv[i] = (vz != vz) ? 0.f : vz;
    }
    if (sf) {
        int np = 0, nn = 0;
#pragma unroll
        for (int i = 0; i < 4; i++) { np += nzv[i] > 0.f; nn += nzv[i] < 0.f; }
        bool ps = np >= nn;
#pragma unroll
        for (int i = 0; i < 4; i++) {
            float fm = (ps ? (nzv[i] > 0.f) : (nzv[i] < 0.f)) ? 1.f : 0.f;
            nxv[i] *= fm; nyv[i] *= fm; nzv[i] *= fm;
        }
    }
    float snx = (nxv[0] + nxv[1]) + (nxv[2] + nxv[3]);
    float sny = (nyv[0] + nyv[1]) + (nyv[2] + nyv[3]);
    float snz = (nzv[0] + nzv[1]) + (nzv[2] + nzv[3]);

    float num = fmaf(snx, a, sny * b);
    float st, ct; cs_atan_core(num, snz, st, ct);
    float nx = st * a, ny = st * b, nz = ct;
    if (nz != nz) { nx = 0.f; ny = 0.f; nz = -1.f; }
    float s = (ny > 0.f) ? -1.f : 1.f;
    onx = nx * s; ony = ny * s; onz = nz * s;
}

__device__ __noinline__ void generic_pixel(const float* __restrict__ depth,
    int r, int c, int h, int w, float fx, float fy, float ifx,
    float cx, float cy, int sf, float& onx, float& ony, float& onz)
{
    const int dy[5] = {0, -1, 0, 0, 1};
    const int dx[5] = {0,  0,-1, 1, 0};
    float Xs[5], Ys[5], Zs[5], Ds[5];
#pragma unroll
    for (int i = 0; i < 5; i++) {
        int rr_ = r + dy[i], cc = c + dx[i];
        bool inb = (rr_ >= 0) & (rr_ < h) & (cc >= 0) & (cc < w);
        float X = 0.f, Y = 0.f, Z = 0.f, D = 0.f;
        if (inb) {
            float z = depth[rr_ * w + cc];
            Z = z;
            Y = z * ((float)rr_ - cy) * ifx;   // reference uses fx for Y too
            X = z * ((float)cc - cx) * ifx;
            if (Y <= 0.f) { Z = 0.f; Y = 0.f; } // X intentionally NOT zeroed
            if (Z != Z) Z = 0.f;
            D = rcpa(Z);                         // inf where Z == 0
        }
        Xs[i] = X; Ys[i] = Y; Zs[i] = Z; Ds[i] = D;
    }
    float nx_t = (Ds[3] - Ds[2]) * fx;
    float ny_t = (Ds[4] - Ds[1]) * fy;
    float Xd[4], Yd[4], Zd[4];
#pragma unroll
    for (int i = 0; i < 4; i++) {
        Xd[i] = Xs[0] - Xs[i + 1];
        Yd[i] = Ys[0] - Ys[i + 1];
        Zd[i] = Zs[0] - Zs[i + 1];
    }
    gen_finish(nx_t, ny_t, Xd, Yd, Zd, sf, onx, ony, onz);
}

__global__ __launch_bounds__(256)
void nim_kernel(const float* __restrict__ depth,
                const float* __restrict__ cam,
                const int*   __restrict__ sf_ptr,
                float* __restrict__ out,
                int h, int w)
{
    int c = blockIdx.x * 32 + threadIdx.x;
    int r = blockIdx.y * 8 + threadIdx.y;
    if (r >= h || c >= w) return;

    float fx = cam[0], fy = cam[4], cx = cam[2], cy = cam[5];
    float ifx = 1.0f / fx;
    int sf = sf_ptr[0];
    int hw = h * w;
    int idx = r * w + c;

    bool interior = (r >= 1) & (r < h - 1) & (c >= 1) & (c < w - 1);

    if (interior) {
        float zc = depth[idx];
        float zl = depth[idx - 1];
        float zr = depth[idx + 1];
        float zu = depth[idx - w];
        float zd = depth[idx + w];

        // NaN-safe positivity of all 5 depths involved in this pixel
        bool ok = (zc > ZMIN) & (zl > ZMIN) & (zr > ZMIN) & (zu > ZMIN) & (zd > ZMIN);

        float fv  = ((float)r       - cy) * ifx;
        float fvm = ((float)(r - 1) - cy) * ifx;
        float fvp = ((float)(r + 1) - cy) * ifx;

        if (ok) {
            if (fvp <= 0.f) {
                // All 5 pixels masked (Y<=0 -> Z=0 -> D=inf) -> NaN cascade ->
                // reference emits exactly (0, 0, -1).
                out[idx]          = 0.f;
                out[idx + hw]     = 0.f;
                out[idx + 2 * hw] = -1.f;
                return;
            }
            if (fvm > 0.f) {
                // Fully unmasked: Z=z, Y=z*fv, X=z*fu, D=1/z.
                float Dl = rcpa(zl), Dr = rcpa(zr);
                float Du = rcpa(zu), Dd = rcpa(zd);
                float nx_t = (Dr - Dl) * fx;
                float ny_t = (Dd - Du) * fy;

                float fuc = ((float)c       - cx) * ifx;
                float ful = ((float)(c - 1) - cx) * ifx;
                float fur = ((float)(c + 1) - cx) * ifx;
                float Xc = zc * fuc;
                float Yc = zc * fv;

                // neighbors: 0:up(-1,0) 1:left(0,-1) 2:right(0,1) 3:down(1,0)
                float Xd[4], Yd[4], Zd[4];
                Zd[0] = zc - zu;  Xd[0] = Zd[0] * fuc;       Yd[0] = fmaf(-zu, fvm, Yc);
                Zd[1] = zc - zl;  Xd[1] = fmaf(-zl, ful, Xc); Yd[1] = Zd[1] * fv;
                Zd[2] = zc - zr;  Xd[2] = fmaf(-zr, fur, Xc); Yd[2] = Zd[2] * fv;
                Zd[3] = zc - zd;  Xd[3] = Zd[3] * fuc;       Yd[3] = fmaf(-zd, fvp, Yc);

                float onx, ony, onz;
                hot_finish(nx_t, ny_t, Xd, Yd, Zd, sf, onx, ony, onz);
                out[idx]          = onx;
                out[idx + hw]     = ony;
                out[idx + 2 * hw] = onz;
                return;
            }
        }
    }

    // Borders, horizon band, pathological depth values.
    float onx, ony, onz;
    generic_pixel(depth, r, c, h, w, fx, fy, ifx, cx, cy, sf, onx, ony, onz);
    out[idx]          = onx;
    out[idx + hw]     = ony;
    out[idx + 2 * hw] = onz;
}

extern "C" void kernel_launch(void* const* d_in, const int* in_sizes, int n_in,
                              void* d_out, int out_size) {
    const float* depth = (const float*)d_in[0];
    const float* cam   = (const float*)d_in[1];
    const int*   sf    = (const int*)d_in[2];
    float* out = (float*)d_out;

    int w = W_IMG;
    int h = in_sizes[0] / w;

    dim3 block(32, 8);
    dim3 grid((w + 31) / 32, (h + 7) / 8);
    nim_kernel<<<grid, block>>>(depth, cam, sf, out, h, w);
}

// round 6
// speedup vs baseline: 1.1823x; 1.1823x over previous
#include <cuda_runtime.h>
#include <math.h>

#define W_IMG 4096
// float(pi) - pi  (cos(pi_f) == -1 exactly, sin(pi_f) == -DPI)
#define DPI 8.742278e-8f
#define ZMIN 1e-12f

__device__ __forceinline__ float rcpa(float x){ float y; asm("rcp.approx.f32 %0, %1;" : "=f"(y) : "f"(x)); return y; }
__device__ __forceinline__ float rsqa(float x){ float y; asm("rsqrt.approx.f32 %0, %1;" : "=f"(y) : "f"(x)); return y; }
// y with sign flipped by sign(x): single LOP3
__device__ __forceinline__ float xsign(float y, float x){
    return __int_as_float(__float_as_int(y) ^ (__float_as_int(x) & 0x80000000u));
}

// ---------- robust sin/cos of atan(num/den): handles inf operands too -------
__device__ __forceinline__ void cs_atan_core(float num, float den, float& sa, float& ca) {
    float an = fabsf(num), ad = fabsf(den);
    bool sw = an > ad;
    float top = sw ? den : num;
    float bot = sw ? num : den;
    float q  = top * rcpa(bot);                 // |q| <= 1, or NaN
    float rr = rsqa(fmaf(q, q, 1.f));
    float sg = copysignf(1.f, num) * copysignf(1.f, den);
    ca = sw ? fabsf(q) * rr : rr;
    sa = sw ? sg * rr : q * rr;
}

// ---------- HOT finisher: nx_t, ny_t guaranteed finite (z > ZMIN) -----------
__device__ __forceinline__ void hot_finish(
    float nx_t, float ny_t,
    const float* Xd, const float* Yd, const float* Zd,
    int sf, float& onx, float& ony, float& onz)
{
    float nt2 = fmaf(nx_t, nx_t, ny_t * ny_t);
    float r0  = rsqa(nt2);
    float ca  = fabsf(nx_t) * r0;           // cos(atan(ny/nx))
    float sa  = xsign(ny_t, nx_t) * r0;     // sin(atan(ny/nx))
    float a   = fmaf(sa, DPI, -ca);         // cos(atan + pi_f)
    float b   = -fmaf(ca, DPI, sa);         // sin(atan + pi_f)

    float rnz[4], nzv[4];
    int npos = 0, nneg = 0;
#pragma unroll
    for (int i = 0; i < 4; i++) {
        float nz_i = -fmaf(nx_t, Xd[i], ny_t * Yd[i]) * rcpa(Zd[i]);
        float rn = rsqa(fmaf(nz_i, nz_i, nt2));
        float v  = nz_i * rn;
        rnz[i] = (rn != rn) ? 0.f : rn;     // NaN rn -> all comps zero
        nzv[i] = (v  != v)  ? 0.f : v;
        npos += nzv[i] > 0.f;
        nneg += nzv[i] < 0.f;
    }

    float srn = 0.f, snz = 0.f;
    if (sf) {
        bool ps = npos >= nneg;
#pragma unroll
        for (int i = 0; i < 4; i++) {
            float fm = (ps ? (nzv[i] > 0.f) : (nzv[i] < 0.f)) ? 1.f : 0.f;
            srn = fmaf(fm, rnz[i], srn);
            snz = fmaf(fm, nzv[i], snz);
        }
    } else {
#pragma unroll
        for (int i = 0; i < 4; i++) { srn += rnz[i]; snz += nzv[i]; }
    }

    // snx*a + sny*b == srn * (-sign(nx_t)) * sqrt(nt2)   (exact; DPI cancels)
    float num = -xsign(srn * (nt2 * r0), nx_t);
    float rr  = rsqa(fmaf(num, num, snz * snz));
    float st  = xsign(num, snz) * rr;       // sin(atan(num/snz))
    float ct  = fabsf(snz) * rr;            // cos(atan(num/snz))
    float nx = st * a, ny = st * b, nz = ct;
    if (nz != nz) { nx = 0.f; ny = 0.f; nz = -1.f; }
    float s = (ny > 0.f) ? -1.f : 1.f;
    onx = nx * s; ony = ny * s; onz = nz * s;
}

// ---------- generic finisher (robust to inf nx_t/ny_t) ----------------------
__device__ __forceinline__ void gen_finish(
    float nx_t, float ny_t,
    const float* Xd, const float* Yd, const float* Zd,
    int sf, float& onx, float& ony, float& onz)
{
    float sa, ca; cs_atan_core(ny_t, nx_t, sa, ca);
    float a = fmaf(sa, DPI, -ca);
    float b = -fmaf(ca, DPI, sa);
    float nt2 = fmaf(nx_t, nx_t, ny_t * ny_t);

    float nxv[4], nyv[4], nzv[4];
#pragma unroll
    for (int i = 0; i < 4; i++) {
        float nz_i = -fmaf(nx_t, Xd[i], ny_t * Yd[i]) * rcpa(Zd[i]);
        float rn = rsqa(fmaf(nz_i, nz_i, nt2));
        float vx = nx_t * rn, vy = ny_t * rn, vz = nz_i * rn;
        nxv[i] = (vx != vx) ? 0.f : vx;
        nyv[i] = (vy != vy) ? 0.f : vy;
        nzv[i] = (vz != vz) ? 0.f : vz;
    }
    if (sf) {
        int np = 0, nn = 0;
#pragma unroll
        for (int i = 0; i < 4; i++) { np += nzv[i] > 0.f; nn += nzv[i] < 0.f; }
        bool ps = np >= nn;
#pragma unroll
        for (int i = 0; i < 4; i++) {
            float fm = (ps ? (nzv[i] > 0.f) : (nzv[i] < 0.f)) ? 1.f : 0.f;
            nxv[i] *= fm; nyv[i] *= fm; nzv[i] *= fm;
        }
    }
    float snx = (nxv[0] + nxv[1]) + (nxv[2] + nxv[3]);
    float sny = (nyv[0] + nyv[1]) + (nyv[2] + nyv[3]);
    float snz = (nzv[0] + nzv[1]) + (nzv[2] + nzv[3]);

    float num = fmaf(snx, a, sny * b);
    float st, ct; cs_atan_core(num, snz, st, ct);
    float nx = st * a, ny = st * b, nz = ct;
    if (nz != nz) { nx = 0.f; ny = 0.f; nz = -1.f; }
    float s = (ny > 0.f) ? -1.f : 1.f;
    onx = nx * s; ony = ny * s; onz = nz * s;
}

__device__ __noinline__ void generic_pixel(const float* __restrict__ depth,
    int r, int c, int h, int w, float fx, float fy, float ifx,
    float cx, float cy, int sf, float& onx, float& ony, float& onz)
{
    const int dy[5] = {0, -1, 0, 0, 1};
    const int dx[5] = {0,  0,-1, 1, 0};
    float Xs[5], Ys[5], Zs[5], Ds[5];
#pragma unroll
    for (int i = 0; i < 5; i++) {
        int rr_ = r + dy[i], cc = c + dx[i];
        bool inb = (rr_ >= 0) & (rr_ < h) & (cc >= 0) & (cc < w);
        float X = 0.f, Y = 0.f, Z = 0.f, D = 0.f;
        if (inb) {
            float z = depth[rr_ * w + cc];
            Z = z;
            Y = z * ((float)rr_ - cy) * ifx;   // reference uses fx for Y too
            X = z * ((float)cc - cx) * ifx;
            if (Y <= 0.f) { Z = 0.f; Y = 0.f; } // X intentionally NOT zeroed
            if (Z != Z) Z = 0.f;
            D = rcpa(Z);                         // inf where Z == 0
        }
        Xs[i] = X; Ys[i] = Y; Zs[i] = Z; Ds[i] = D;
    }
    float nx_t = (Ds[3] - Ds[2]) * fx;
    float ny_t = (Ds[4] - Ds[1]) * fy;
    float Xd[4], Yd[4], Zd[4];
#pragma unroll
    for (int i = 0; i < 4; i++) {
        Xd[i] = Xs[0] - Xs[i + 1];
        Yd[i] = Ys[0] - Ys[i + 1];
        Zd[i] = Zs[0] - Zs[i + 1];
    }
    gen_finish(nx_t, ny_t, Xd, Yd, Zd, sf, onx, ony, onz);
}

__global__ __launch_bounds__(128)
void nim_kernel(const float* __restrict__ depth,
                const float* __restrict__ cam,
                const int*   __restrict__ sf_ptr,
                float* __restrict__ out,
                int h, int w)
{
    int r  = blockIdx.y * 4 + threadIdx.y;
    int c0 = (blockIdx.x * 32 + threadIdx.x) * 4;
    if (r >= h || c0 + 3 >= w) return;

    float fx = cam[0], fy = cam[4], cx = cam[2], cy = cam[5];
    float ifx = 1.0f / fx;
    int sf = sf_ptr[0];
    int hw = h * w;
    int base = r * w + c0;

    bool interior = (r >= 1) & (r < h - 1) & (c0 >= 4) & (c0 <= w - 8);

    if (interior) {
        float4 zu4 = *(const float4*)(depth + base - w);
        float4 zd4 = *(const float4*)(depth + base + w);
        float4 zm4 = *(const float4*)(depth + base);
        float  zml = depth[base - 1];
        float  zmr = depth[base + 4];

        float zu[4] = {zu4.x, zu4.y, zu4.z, zu4.w};
        float zd[4] = {zd4.x, zd4.y, zd4.z, zd4.w};
        float zm[6] = {zml, zm4.x, zm4.y, zm4.z, zm4.w, zmr};

        float fv0 = ((float)r       - cy) * ifx;
        float fvm = ((float)(r - 1) - cy) * ifx;
        float fvp = ((float)(r + 1) - cy) * ifx;

        // NaN-safe: all depths comfortably positive (keeps nx_t/ny_t finite,
        // nt2 un-overflowed in the hot finisher)
        bool allpos = (zu[0] > ZMIN) & (zu[1] > ZMIN) & (zu[2] > ZMIN) & (zu[3] > ZMIN)
                    & (zd[0] > ZMIN) & (zd[1] > ZMIN) & (zd[2] > ZMIN) & (zd[3] > ZMIN)
                    & (zm[0] > ZMIN) & (zm[1] > ZMIN) & (zm[2] > ZMIN)
                    & (zm[3] > ZMIN) & (zm[4] > ZMIN) & (zm[5] > ZMIN);

        if (allpos && fvp <= 0.f) {
            // Whole neighborhood masked (Y<=0 -> Z=0 -> D=inf) -> NaN cascade
            // -> reference emits exactly (0, 0, -1).
            float4 zro = make_float4(0.f, 0.f, 0.f, 0.f);
            float4 neg = make_float4(-1.f, -1.f, -1.f, -1.f);
            *(float4*)(out + base)          = zro;
            *(float4*)(out + base + hw)     = zro;
            *(float4*)(out + base + 2 * hw) = neg;
            return;
        }

        if (allpos && fvm > 0.f) {
            float Dm[6], Xm[6], Du[4], Dd[4];
#pragma unroll
            for (int j = 0; j < 6; j++) {
                float fu = ((float)(c0 - 1 + j) - cx) * ifx;
                Xm[j] = zm[j] * fu;
                Dm[j] = rcpa(zm[j]);
            }
#pragma unroll
            for (int p = 0; p < 4; p++) { Du[p] = rcpa(zu[p]); Dd[p] = rcpa(zd[p]); }

            float4 ox, oy, oz;
            float* oxp = &ox.x; float* oyp = &oy.x; float* ozp = &oz.x;
#pragma unroll
            for (int p = 0; p < 4; p++) {
                float zc  = zm[p + 1];
                float fuc = ((float)(c0 + p) - cx) * ifx;

                float nx_t = (Dm[p + 2] - Dm[p]) * fx;
                float ny_t = (Dd[p] - Du[p]) * fy;

                // neighbors: 0:up(-1,0) 1:left(0,-1) 2:right(0,1) 3:down(1,0)
                float Xd[4], Yd[4], Zd[4];
                Zd[0] = zc - zu[p];
                Xd[0] = Zd[0] * fuc;
                Yd[0] = fmaf(zc, fv0, -(zu[p] * fvm));
                Zd[1] = zc - zm[p];
                Xd[1] = Xm[p + 1] - Xm[p];
                Yd[1] = Zd[1] * fv0;
                Zd[2] = zc - zm[p + 2];
                Xd[2] = Xm[p + 1] - Xm[p + 2];
                Yd[2] = Zd[2] * fv0;
                Zd[3] = zc - zd[p];
                Xd[3] = Zd[3] * fuc;
                Yd[3] = fmaf(zc, fv0, -(zd[p] * fvp));

                hot_finish(nx_t, ny_t, Xd, Yd, Zd, sf, oxp[p], oyp[p], ozp[p]);
            }
            *(float4*)(out + base)          = ox;
            *(float4*)(out + base + hw)     = oy;
            *(float4*)(out + base + 2 * hw) = oz;
            return;
        }
    }

    // Borders, horizon band, pathological depth values.
    for (int p = 0; p < 4; p++) {
        float onx, ony, onz;
        generic_pixel(depth, r, c0 + p, h, w, fx, fy, ifx, cx, cy, sf, onx, ony, onz);
        out[base + p]          = onx;
        out[base + p + hw]     = ony;
        out[base + p + 2 * hw] = onz;
    }
}

extern "C" void kernel_launch(void* const* d_in, const int* in_sizes, int n_in,
                              void* d_out, int out_size) {
    const float* depth = (const float*)d_in[0];
    const float* cam   = (const float*)d_in[1];
    const int*   sf    = (const int*)d_in[2];
    float* out = (float*)d_out;

    int w = W_IMG;
    int h = in_sizes[0] / w;

    dim3 block(32, 4);
    dim3 grid((w + 127) / 128, (h + 3) / 4);
    nim_kernel<<<grid, block>>>(depth, cam, sf, out, h, w);
}

// round 7
// speedup vs baseline: 1.2696x; 1.0739x over previous
#include <cuda_runtime.h>
#include <math.h>

#define W_IMG 4096
// float(pi) - pi  (cos(pi_f) == -1 exactly, sin(pi_f) == -DPI)
#define DPI 8.742278e-8f
#define ZMIN 1e-12f

__device__ __forceinline__ float rcpa(float x){ float y; asm("rcp.approx.f32 %0, %1;" : "=f"(y) : "f"(x)); return y; }
__device__ __forceinline__ float rsqa(float x){ float y; asm("rsqrt.approx.f32 %0, %1;" : "=f"(y) : "f"(x)); return y; }
// y with sign flipped by sign(x): single LOP3
__device__ __forceinline__ float xsign(float y, float x){
    return __int_as_float(__float_as_int(y) ^ (__float_as_int(x) & 0x80000000u));
}

// ---------- robust sin/cos of atan(num/den): handles inf operands too -------
__device__ __forceinline__ void cs_atan_core(float num, float den, float& sa, float& ca) {
    float an = fabsf(num), ad = fabsf(den);
    bool sw = an > ad;
    float top = sw ? den : num;
    float bot = sw ? num : den;
    float q  = top * rcpa(bot);                 // |q| <= 1, or NaN
    float rr = rsqa(fmaf(q, q, 1.f));
    float sg = copysignf(1.f, num) * copysignf(1.f, den);
    ca = sw ? fabsf(q) * rr : rr;
    sa = sw ? sg * rr : q * rr;
}

// ---------- HOT finisher: nx_t, ny_t guaranteed finite (z > ZMIN) -----------
__device__ __forceinline__ float3 hot_finish(
    float nx_t, float ny_t,
    const float* Xd, const float* Yd, const float* Zd, int sf)
{
    float nt2 = fmaf(nx_t, nx_t, ny_t * ny_t);
    float r0  = rsqa(nt2);
    float ca  = fabsf(nx_t) * r0;           // cos(atan(ny/nx))
    float sa  = xsign(ny_t, nx_t) * r0;     // sin(atan(ny/nx))
    float a   = fmaf(sa, DPI, -ca);         // cos(atan + pi_f)
    float b   = -fmaf(ca, DPI, sa);         // sin(atan + pi_f)

    float rnz[4], nzv[4];
    int npos = 0, nneg = 0;
#pragma unroll
    for (int i = 0; i < 4; i++) {
        float nz_i = -fmaf(nx_t, Xd[i], ny_t * Yd[i]) * rcpa(Zd[i]);
        float rn = rsqa(fmaf(nz_i, nz_i, nt2));
        float v  = nz_i * rn;
        bool pv  = (v != v);                // covers nz_i NaN and nz_i inf
        rnz[i] = pv ? 0.f : rn;             // rn==0 when nz_i inf, so safe
        nzv[i] = pv ? 0.f : v;
        npos += nzv[i] > 0.f;
        nneg += nzv[i] < 0.f;
    }

    float srn = 0.f, snz = 0.f;
    if (sf) {
        bool ps = npos >= nneg;
#pragma unroll
        for (int i = 0; i < 4; i++) {
            float fm = (ps ? (nzv[i] > 0.f) : (nzv[i] < 0.f)) ? 1.f : 0.f;
            srn = fmaf(fm, rnz[i], srn);
            snz = fmaf(fm, nzv[i], snz);
        }
    } else {
#pragma unroll
        for (int i = 0; i < 4; i++) { srn += rnz[i]; snz += nzv[i]; }
    }

    // snx*a + sny*b == srn * (-sign(nx_t)) * sqrt(nt2)   (exact; DPI cancels)
    float num = -xsign(srn * (nt2 * r0), nx_t);
    float rr  = rsqa(fmaf(num, num, snz * snz));
    float st  = xsign(num, snz) * rr;       // sin(atan(num/snz))
    float ct  = fabsf(snz) * rr;            // cos(atan(num/snz))
    float nx = st * a, ny = st * b, nz = ct;
    if (nz != nz) { nx = 0.f; ny = 0.f; nz = -1.f; }
    float s = (ny > 0.f) ? -1.f : 1.f;
    return make_float3(nx * s, ny * s, nz * s);
}

// ---------- generic finisher (robust to inf nx_t/ny_t) ----------------------
__device__ __forceinline__ void gen_finish(
    float nx_t, float ny_t,
    const float* Xd, const float* Yd, const float* Zd,
    int sf, float& onx, float& ony, float& onz)
{
    float sa, ca; cs_atan_core(ny_t, nx_t, sa, ca);
    float a = fmaf(sa, DPI, -ca);
    float b = -fmaf(ca, DPI, sa);
    float nt2 = fmaf(nx_t, nx_t, ny_t * ny_t);

    float nxv[4], nyv[4], nzv[4];
#pragma unroll
    for (int i = 0; i < 4; i++) {
        float nz_i = -fmaf(nx_t, Xd[i], ny_t * Yd[i]) * rcpa(Zd[i]);
        float rn = rsqa(fmaf(nz_i, nz_i, nt2));
        float vx = nx_t * rn, vy = ny_t * rn, vz = nz_i * rn;
        nxv[i] = (vx != vx) ? 0.f : vx;
        nyv[i] = (vy != vy) ? 0.f : vy;
        nzv[i] = (vz != vz) ? 0.f : vz;
    }
    if (sf) {
        int np = 0, nn = 0;
#pragma unroll
        for (int i = 0; i < 4; i++) { np += nzv[i] > 0.f; nn += nzv[i] < 0.f; }
        bool ps = np >= nn;
#pragma unroll
        for (int i = 0; i < 4; i++) {
            float fm = (ps ? (nzv[i] > 0.f) : (nzv[i] < 0.f)) ? 1.f : 0.f;
            nxv[i] *= fm; nyv[i] *= fm; nzv[i] *= fm;
        }
    }
    float snx = (nxv[0] + nxv[1]) + (nxv[2] + nxv[3]);
    float sny = (nyv[0] + nyv[1]) + (nyv[2] + nyv[3]);
    float snz = (nzv[0] + nzv[1]) + (nzv[2] + nzv[3]);

    float num = fmaf(snx, a, sny * b);
    float st, ct; cs_atan_core(num, snz, st, ct);
    float nx = st * a, ny = st * b, nz = ct;
    if (nz != nz) { nx = 0.f; ny = 0.f; nz = -1.f; }
    float s = (ny > 0.f) ? -1.f : 1.f;
    onx = nx * s; ony = ny * s; onz = nz * s;
}

__device__ __noinline__ void generic_pixel(const float* __restrict__ depth,
    int r, int c, int h, int w, float fx, float fy, float ifx,
    float cx, float cy, int sf, float& onx, float& ony, float& onz)
{
    const int dy[5] = {0, -1, 0, 0, 1};
    const int dx[5] = {0,  0,-1, 1, 0};
    float Xs[5], Ys[5], Zs[5], Ds[5];
#pragma unroll
    for (int i = 0; i < 5; i++) {
        int rr_ = r + dy[i], cc = c + dx[i];
        bool inb = (rr_ >= 0) & (rr_ < h) & (cc >= 0) & (cc < w);
        float X = 0.f, Y = 0.f, Z = 0.f, D = 0.f;
        if (inb) {
            float z = depth[rr_ * w + cc];
            Z = z;
            Y = z * ((float)rr_ - cy) * ifx;   // reference uses fx for Y too
            X = z * ((float)cc - cx) * ifx;
            if (Y <= 0.f) { Z = 0.f; Y = 0.f; } // X intentionally NOT zeroed
            if (Z != Z) Z = 0.f;
            D = rcpa(Z);                         // inf where Z == 0
        }
        Xs[i] = X; Ys[i] = Y; Zs[i] = Z; Ds[i] = D;
    }
    float nx_t = (Ds[3] - Ds[2]) * fx;
    float ny_t = (Ds[4] - Ds[1]) * fy;
    float Xd[4], Yd[4], Zd[4];
#pragma unroll
    for (int i = 0; i < 4; i++) {
        Xd[i] = Xs[0] - Xs[i + 1];
        Yd[i] = Ys[0] - Ys[i + 1];
        Zd[i] = Zs[0] - Zs[i + 1];
    }
    gen_finish(nx_t, ny_t, Xd, Yd, Zd, sf, onx, ony, onz);
}

__global__ __launch_bounds__(128)
void nim_kernel(const float* __restrict__ depth,
                const float* __restrict__ cam,
                const int*   __restrict__ sf_ptr,
                float* __restrict__ out,
                int h, int w)
{
    int r  = blockIdx.y * 4 + threadIdx.y;
    int c0 = (blockIdx.x * 32 + threadIdx.x) * 4;
    if (r >= h || c0 + 3 >= w) return;

    float fx = cam[0], fy = cam[4], cx = cam[2], cy = cam[5];
    float ifx = 1.0f / fx;
    int sf = sf_ptr[0];
    int hw = h * w;
    int base = r * w + c0;

    bool interior = (r >= 1) & (r < h - 1) & (c0 >= 4) & (c0 <= w - 8);

    if (interior) {
        float4 zu4 = *(const float4*)(depth + base - w);
        float4 zd4 = *(const float4*)(depth + base + w);
        float4 zm4 = *(const float4*)(depth + base);
        float  zml = depth[base - 1];
        float  zmr = depth[base + 4];

        float zu[4] = {zu4.x, zu4.y, zu4.z, zu4.w};
        float zd[4] = {zd4.x, zd4.y, zd4.z, zd4.w};
        float zm[6] = {zml, zm4.x, zm4.y, zm4.z, zm4.w, zmr};

        float fv0 = ((float)r       - cy) * ifx;
        float fvm = ((float)(r - 1) - cy) * ifx;
        float fvp = ((float)(r + 1) - cy) * ifx;

        // NaN-safe: all depths comfortably positive (keeps nx_t/ny_t finite,
        // nt2 un-overflowed in the hot finisher)
        bool allpos = (zu[0] > ZMIN) & (zu[1] > ZMIN) & (zu[2] > ZMIN) & (zu[3] > ZMIN)
                    & (zd[0] > ZMIN) & (zd[1] > ZMIN) & (zd[2] > ZMIN) & (zd[3] > ZMIN)
                    & (zm[0] > ZMIN) & (zm[1] > ZMIN) & (zm[2] > ZMIN)
                    & (zm[3] > ZMIN) & (zm[4] > ZMIN) & (zm[5] > ZMIN);

        if (allpos && fvp <= 0.f) {
            // Whole neighborhood masked (Y<=0 -> Z=0 -> D=inf) -> NaN cascade
            // -> reference emits exactly (0, 0, -1).
            float4 zro = make_float4(0.f, 0.f, 0.f, 0.f);
            float4 neg = make_float4(-1.f, -1.f, -1.f, -1.f);
            *(float4*)(out + base)          = zro;
            *(float4*)(out + base + hw)     = zro;
            *(float4*)(out + base + 2 * hw) = neg;
            return;
        }

        if (allpos && fvm > 0.f) {
            // fu ladder: fu[j] = (c0-1+j - cx) * ifx, built incrementally
            float fu0 = ((float)(c0 - 1) - cx) * ifx;
            float fu1 = fu0 + ifx;
            float fu2 = fu1 + ifx;
            float fu3 = fu2 + ifx;
            float fu4 = fu3 + ifx;
            float fu5 = fu4 + ifx;
            float fuA[6] = {fu0, fu1, fu2, fu3, fu4, fu5};

            float Dm[6], Xm[6], Du[4], Dd[4];
#pragma unroll
            for (int j = 0; j < 6; j++) {
                Xm[j] = zm[j] * fuA[j];
                Dm[j] = rcpa(zm[j]);
            }
#pragma unroll
            for (int p = 0; p < 4; p++) { Du[p] = rcpa(zu[p]); Dd[p] = rcpa(zd[p]); }

            float3 o0, o1, o2, o3;
#pragma unroll
            for (int p = 0; p < 4; p++) {
                float zc  = zm[p + 1];
                float fuc = fuA[p + 1];

                float nx_t = (Dm[p + 2] - Dm[p]) * fx;
                float ny_t = (Dd[p] - Du[p]) * fy;

                // neighbors: 0:up(-1,0) 1:left(0,-1) 2:right(0,1) 3:down(1,0)
                float Xd[4], Yd[4], Zd[4];
                Zd[0] = zc - zu[p];
                Xd[0] = Zd[0] * fuc;
                Yd[0] = fmaf(zc, fv0, -(zu[p] * fvm));
                Zd[1] = zc - zm[p];
                Xd[1] = Xm[p + 1] - Xm[p];
                Yd[1] = Zd[1] * fv0;
                Zd[2] = zc - zm[p + 2];
                Xd[2] = Xm[p + 1] - Xm[p + 2];
                Yd[2] = Zd[2] * fv0;
                Zd[3] = zc - zd[p];
                Xd[3] = Zd[3] * fuc;
                Yd[3] = fmaf(zc, fv0, -(zd[p] * fvp));

                float3 o = hot_finish(nx_t, ny_t, Xd, Yd, Zd, sf);
                if      (p == 0) o0 = o;
                else if (p == 1) o1 = o;
                else if (p == 2) o2 = o;
                else             o3 = o;
            }
            *(float4*)(out + base)          = make_float4(o0.x, o1.x, o2.x, o3.x);
            *(float4*)(out + base + hw)     = make_float4(o0.y, o1.y, o2.y, o3.y);
            *(float4*)(out + base + 2 * hw) = make_float4(o0.z, o1.z, o2.z, o3.z);
            return;
        }
    }

    // Borders, horizon band, pathological depth values.
    for (int p = 0; p < 4; p++) {
        float onx, ony, onz;
        generic_pixel(depth, r, c0 + p, h, w, fx, fy, ifx, cx, cy, sf, onx, ony, onz);
        out[base + p]          = onx;
        out[base + p + hw]     = ony;
        out[base + p + 2 * hw] = onz;
    }
}

extern "C" void kernel_launch(void* const* d_in, const int* in_sizes, int n_in,
                              void* d_out, int out_size) {
    const float* depth = (const float*)d_in[0];
    const float* cam   = (const float*)d_in[1];
    const int*   sf    = (const int*)d_in[2];
    float* out = (float*)d_out;

    int w = W_IMG;
    int h = in_sizes[0] / w;

    dim3 block(32, 4);
    dim3 grid((w + 127) / 128, (h + 3) / 4);
    nim_kernel<<<grid, block>>>(depth, cam, sf, out, h, w);
}